// round 8
// baseline (speedup 1.0000x reference)
#include <cuda_runtime.h>
#include <math.h>

#define BATCH 4
#define SEQ   4096
#define EMB   512
#define HD    64
#define NSPLIT 4

__device__ float g_q[BATCH * SEQ * HD];
__device__ float g_k[BATCH * SEQ * HD];
__device__ float g_v[BATCH * SEQ * HD];
__device__ float g_wt[3 * HD * EMB];                  // pre-rounded tf32 weights
__device__ float g_part[NSPLIT * BATCH * SEQ * HD];   // unnormalized O partials
__device__ float g_lsum[NSPLIT * BATCH * SEQ];        // exp-sum partials

// ---------------------------------------------------------------------------
__device__ __forceinline__ unsigned f2tf(float x) {
    unsigned r;
    asm("cvt.rna.tf32.f32 %0, %1;" : "=r"(r) : "f"(x));
    return r;
}
__device__ __forceinline__ float ex2(float x) {
    float r;
    asm("ex2.approx.ftz.f32 %0, %1;" : "=f"(r) : "f"(x));
    return r;
}

__device__ __forceinline__ void mma_tf32(float c[4],
                                         unsigned a0, unsigned a1,
                                         unsigned a2, unsigned a3,
                                         unsigned b0, unsigned b1) {
    asm volatile(
        "mma.sync.aligned.m16n8k8.row.col.f32.tf32.tf32.f32 "
        "{%0,%1,%2,%3}, {%4,%5,%6,%7}, {%8,%9}, {%0,%1,%2,%3};"
        : "+f"(c[0]), "+f"(c[1]), "+f"(c[2]), "+f"(c[3])
        : "r"(a0), "r"(a1), "r"(a2), "r"(a3), "r"(b0), "r"(b1));
}

#define CP_COMMIT() asm volatile("cp.async.commit_group;" ::: "memory")
#define CP_WAIT1()  asm volatile("cp.async.wait_group 1;" ::: "memory")

// ---------------------------------------------------------------------------
// Weight prepass: pre-round WQ/WK/WV to tf32 (raw-copyable thereafter).
// ---------------------------------------------------------------------------
__global__ __launch_bounds__(256) void wcvt_kernel(
    const float* __restrict__ WQ,
    const float* __restrict__ WK,
    const float* __restrict__ WV)
{
    int idx = blockIdx.x * 256 + threadIdx.x;       // 24576 float4
    int m = idx >> 13;                              // 8192 float4 per matrix
    int r = idx & 8191;
    const float* s = (m == 0) ? WQ : (m == 1) ? WK : WV;
    float4 v = reinterpret_cast<const float4*>(s)[r];
    uint4 t = { f2tf(v.x), f2tf(v.y), f2tf(v.z), f2tf(v.w) };
    reinterpret_cast<uint4*>(g_wt)[idx] = t;
}

// ---------------------------------------------------------------------------
// tf32 projection, m32 warp tiles: CTA = 64 threads (2 warps x 32 rows).
// X & pre-rounded W stream via cp.async (double-buffered); only X fragments
// need cvt (64 per warp-chunk for 128 mma).
// ---------------------------------------------------------------------------
#define PPX 68
#define XBUF (64 * PPX)
#define WBUF (64 * PPX)
#define PROJ_SMEM_BYTES ((2 * XBUF + 2 * WBUF) * 4)
#define PNCHUNK (EMB / 64)   // 8

__device__ __forceinline__ void proj_cp(float* Xd, float* Wd,
                                        const float* xs, const float* ws,
                                        int tid) {
    unsigned xa = (unsigned)__cvta_generic_to_shared(Xd);
    unsigned wa = (unsigned)__cvta_generic_to_shared(Wd);
    #pragma unroll
    for (int i = 0; i < 16; i++) {
        int f = tid + 64 * i;            // 1024 float4 = 64 rows x 16
        int row = f >> 4, c4 = f & 15;
        asm volatile("cp.async.cg.shared.global [%0], [%1], 16;" ::
            "r"(xa + (unsigned)((row * PPX + c4 * 4) * 4)),
            "l"(xs + (size_t)row * EMB + c4 * 4) : "memory");
        asm volatile("cp.async.cg.shared.global [%0], [%1], 16;" ::
            "r"(wa + (unsigned)((row * PPX + c4 * 4) * 4)),
            "l"(ws + (size_t)row * EMB + c4 * 4) : "memory");
    }
}

__global__ __launch_bounds__(64) void proj_mma_kernel(const float* __restrict__ x)
{
    extern __shared__ float psm[];
    float* Xb[2] = { psm, psm + XBUF };
    float* Wb[2] = { psm + 2 * XBUF, psm + 2 * XBUF + WBUF };

    const int y = blockIdx.y;
    float* out = (y == 0) ? g_q : (y == 1) ? g_k : g_v;
    const float* wbase = g_wt + y * HD * EMB;

    const int tid  = threadIdx.x;
    const int lane = tid & 31;
    const int warp = tid >> 5;
    const int g    = lane >> 2;
    const int tq   = lane & 3;
    const int bm   = blockIdx.x * 64;
    const int rw   = 32 * warp;

    const float* xbase = x + (size_t)bm * EMB;

    float acc[2][8][4];
    #pragma unroll
    for (int h = 0; h < 2; h++)
        #pragma unroll
        for (int n = 0; n < 8; n++)
            #pragma unroll
            for (int j = 0; j < 4; j++) acc[h][n][j] = 0.0f;

    proj_cp(Xb[0], Wb[0], xbase, wbase, tid);
    CP_COMMIT();

    for (int c = 0; c < PNCHUNK; c++) {
        __syncthreads();              // prior readers of buf (c+1)&1 done
        if (c + 1 < PNCHUNK)
            proj_cp(Xb[(c + 1) & 1], Wb[(c + 1) & 1],
                    xbase + (c + 1) * 64, wbase + (c + 1) * 64, tid);
        CP_COMMIT();
        CP_WAIT1();                   // this chunk's copies done
        __syncthreads();

        const float*    Xf = Xb[c & 1];
        const unsigned* Wu = reinterpret_cast<const unsigned*>(Wb[c & 1]);

        unsigned xa[2][8][4];
        #pragma unroll
        for (int h = 0; h < 2; h++) {
            int ra = rw + 16 * h + g;
            #pragma unroll
            for (int kc = 0; kc < 8; kc++) {
                xa[h][kc][0] = f2tf(Xf[(ra)     * PPX + 8 * kc + tq]);
                xa[h][kc][1] = f2tf(Xf[(ra + 8) * PPX + 8 * kc + tq]);
                xa[h][kc][2] = f2tf(Xf[(ra)     * PPX + 8 * kc + tq + 4]);
                xa[h][kc][3] = f2tf(Xf[(ra + 8) * PPX + 8 * kc + tq + 4]);
            }
        }
        #pragma unroll
        for (int n = 0; n < 8; n++) {
            #pragma unroll
            for (int kc = 0; kc < 8; kc++) {
                unsigned b0 = Wu[(8 * n + g) * PPX + 8 * kc + tq];
                unsigned b1 = Wu[(8 * n + g) * PPX + 8 * kc + tq + 4];
                mma_tf32(acc[0][n], xa[0][kc][0], xa[0][kc][1], xa[0][kc][2], xa[0][kc][3], b0, b1);
                mma_tf32(acc[1][n], xa[1][kc][0], xa[1][kc][1], xa[1][kc][2], xa[1][kc][3], b0, b1);
            }
        }
    }

    // store PRE-ROUNDED tf32 (attention consumes without cvt)
    #pragma unroll
    for (int h = 0; h < 2; h++) {
        int ra = rw + 16 * h + g;
        float* o0 = out + (size_t)(bm + ra)     * HD;
        float* o1 = out + (size_t)(bm + ra + 8) * HD;
        #pragma unroll
        for (int n = 0; n < 8; n++) {
            int cc = 8 * n + 2 * tq;
            float2 w0 = { __uint_as_float(f2tf(acc[h][n][0])),
                          __uint_as_float(f2tf(acc[h][n][1])) };
            float2 w1 = { __uint_as_float(f2tf(acc[h][n][2])),
                          __uint_as_float(f2tf(acc[h][n][3])) };
            *reinterpret_cast<float2*>(&o0[cc]) = w0;
            *reinterpret_cast<float2*>(&o1[cc]) = w1;
        }
    }
}

// ---------------------------------------------------------------------------
// Attention: tf32 mma, m32 warp tile, CTA = 128 Q rows / 4 warps, split-KV
// (NSPLIT=4 -> L2-resident partials), cp.async double-buffered K/V,
// shuffle S->P conversion, P fed as raw fp32 bits (HW tf32 truncation).
// ---------------------------------------------------------------------------
#define PK   68
#define PV   72
#define KBUF (64 * PK)
#define VBUF (64 * PV)
#define ATTN_SMEM_BYTES ((2 * KBUF + 2 * VBUF) * 4)

__device__ __forceinline__ void attn_load_async(float* Kd, float* Vd,
                                                const float* kg, const float* vg,
                                                int tid) {
    unsigned ka = (unsigned)__cvta_generic_to_shared(Kd);
    unsigned va = (unsigned)__cvta_generic_to_shared(Vd);
    #pragma unroll
    for (int i = 0; i < 8; i++) {
        int f = tid + 128 * i;           // 1024 float4 = 64 rows x 16
        int row = f >> 4, c4 = f & 15;
        asm volatile("cp.async.cg.shared.global [%0], [%1], 16;" ::
            "r"(ka + (unsigned)((row * PK + c4 * 4) * 4)),
            "l"(kg + row * HD + c4 * 4) : "memory");
        asm volatile("cp.async.cg.shared.global [%0], [%1], 16;" ::
            "r"(va + (unsigned)((row * PV + c4 * 4) * 4)),
            "l"(vg + row * HD + c4 * 4) : "memory");
    }
}

__global__ __launch_bounds__(128) void attn_mma_kernel()
{
    extern __shared__ float sm[];
    float* Kb[2] = { sm, sm + KBUF };
    float* Vb[2] = { sm + 2 * KBUF, sm + 2 * KBUF + VBUF };

    const int tid  = threadIdx.x;
    const int lane = tid & 31;
    const int warp = tid >> 5;
    const int g    = lane >> 2;
    const int tq   = lane & 3;
    const int b    = blockIdx.y;
    const int q0   = blockIdx.x * 128;
    const int z    = blockIdx.z;
    const int nt   = 64 / NSPLIT;        // 16 tiles per split

    const float* qg  = g_q + ((size_t)b * SEQ + q0) * HD;
    const float* kgb = g_k + ((size_t)b * SEQ + (size_t)z * nt * 64) * HD;
    const float* vgb = g_v + ((size_t)b * SEQ + (size_t)z * nt * 64) * HD;

    const int rw = 32 * warp;
    unsigned qa[2][8][4];
    #pragma unroll
    for (int h = 0; h < 2; h++) {
        int ra = rw + 16 * h + g;
        #pragma unroll
        for (int ks = 0; ks < 8; ks++) {
            qa[h][ks][0] = __float_as_uint(qg[(ra)     * HD + 8 * ks + tq]);
            qa[h][ks][1] = __float_as_uint(qg[(ra + 8) * HD + 8 * ks + tq]);
            qa[h][ks][2] = __float_as_uint(qg[(ra)     * HD + 8 * ks + tq + 4]);
            qa[h][ks][3] = __float_as_uint(qg[(ra + 8) * HD + 8 * ks + tq + 4]);
        }
    }

    float oacc[2][8][4];
    #pragma unroll
    for (int h = 0; h < 2; h++)
        #pragma unroll
        for (int n = 0; n < 8; n++)
            #pragma unroll
            for (int j = 0; j < 4; j++) oacc[h][n][j] = 0.0f;
    float ls[2][2] = {{0.f, 0.f}, {0.f, 0.f}};

    attn_load_async(Kb[0], Vb[0], kgb, vgb, tid);
    CP_COMMIT();

    const float C = 0.18033688f;   // 0.125 * log2(e)

    for (int tt = 0; tt < nt; tt++) {
        __syncthreads();
        if (tt + 1 < nt)
            attn_load_async(Kb[(tt + 1) & 1], Vb[(tt + 1) & 1],
                            kgb + (size_t)(tt + 1) * 64 * HD,
                            vgb + (size_t)(tt + 1) * 64 * HD, tid);
        CP_COMMIT();
        CP_WAIT1();
        __syncthreads();

        const unsigned* Ku = reinterpret_cast<const unsigned*>(Kb[tt & 1]);
        const unsigned* Vu = reinterpret_cast<const unsigned*>(Vb[tt & 1]);

        #pragma unroll
        for (int nb = 0; nb < 8; nb++) {
            // ---- S block: both halves share the K B-fragments ----
            float cf[2][4] = {{0.f,0.f,0.f,0.f},{0.f,0.f,0.f,0.f}};
            #pragma unroll
            for (int kc = 0; kc < 8; kc++) {
                unsigned b0 = Ku[(8 * nb + g) * PK + 8 * kc + tq];
                unsigned b1 = Ku[(8 * nb + g) * PK + 8 * kc + tq + 4];
                mma_tf32(cf[0], qa[0][kc][0], qa[0][kc][1], qa[0][kc][2], qa[0][kc][3], b0, b1);
                mma_tf32(cf[1], qa[1][kc][0], qa[1][kc][1], qa[1][kc][2], qa[1][kc][3], b0, b1);
            }

            // ---- exp + C-frag -> A-frag conversion; P passed as raw bits ----
            unsigned pa[2][4];
            #pragma unroll
            for (int h = 0; h < 2; h++) {
                float e0 = ex2(cf[h][0] * C);
                float e1 = ex2(cf[h][1] * C);
                float e2 = ex2(cf[h][2] * C);
                float e3 = ex2(cf[h][3] * C);
                ls[h][0] += e0 + e1;
                ls[h][1] += e2 + e3;
                int hh = tq >> 1;
                float a0  = __shfl_sync(0xffffffffu, e0, hh, 4);
                float a1  = __shfl_sync(0xffffffffu, e1, hh, 4);
                float b0f = __shfl_sync(0xffffffffu, e0, hh + 2, 4);
                float b1f = __shfl_sync(0xffffffffu, e1, hh + 2, 4);
                float c0f = __shfl_sync(0xffffffffu, e2, hh, 4);
                float c1f = __shfl_sync(0xffffffffu, e3, hh, 4);
                float d0f = __shfl_sync(0xffffffffu, e2, hh + 2, 4);
                float d1f = __shfl_sync(0xffffffffu, e3, hh + 2, 4);
                bool odd = (tq & 1);
                pa[h][0] = __float_as_uint(odd ? a1  : a0);    // P[rA][8nb+tq]
                pa[h][1] = __float_as_uint(odd ? c1f : c0f);   // P[rB][8nb+tq]
                pa[h][2] = __float_as_uint(odd ? b1f : b0f);   // P[rA][8nb+tq+4]
                pa[h][3] = __float_as_uint(odd ? d1f : d0f);   // P[rB][8nb+tq+4]
            }

            // ---- O += P(:,nb) * V(nb,:) ; both halves share V B-frags ----
            #pragma unroll
            for (int nd = 0; nd < 8; nd++) {
                unsigned vb0 = Vu[(8 * nb + tq)     * PV + 8 * nd + g];
                unsigned vb1 = Vu[(8 * nb + tq + 4) * PV + 8 * nd + g];
                mma_tf32(oacc[0][nd], pa[0][0], pa[0][1], pa[0][2], pa[0][3], vb0, vb1);
                mma_tf32(oacc[1][nd], pa[1][0], pa[1][1], pa[1][2], pa[1][3], vb0, vb1);
            }
        }
    }

    // ---- epilogue: quad-reduce sums, write unnormalized partials ----
    const size_t rowbase = (size_t)z * BATCH * SEQ + (size_t)b * SEQ + q0;
    #pragma unroll
    for (int h = 0; h < 2; h++) {
        float l0 = ls[h][0], l1 = ls[h][1];
        l0 += __shfl_xor_sync(0xffffffffu, l0, 1);
        l0 += __shfl_xor_sync(0xffffffffu, l0, 2);
        l1 += __shfl_xor_sync(0xffffffffu, l1, 1);
        l1 += __shfl_xor_sync(0xffffffffu, l1, 2);
        int ra = rw + 16 * h + g;
        if (tq == 0) {
            g_lsum[rowbase + ra]     = l0;
            g_lsum[rowbase + ra + 8] = l1;
        }
        float* o0 = g_part + (rowbase + ra)     * HD;
        float* o1 = g_part + (rowbase + ra + 8) * HD;
        #pragma unroll
        for (int n = 0; n < 8; n++) {
            int cc = 8 * n + 2 * tq;
            *reinterpret_cast<float2*>(&o0[cc]) = make_float2(oacc[h][n][0], oacc[h][n][1]);
            *reinterpret_cast<float2*>(&o1[cc]) = make_float2(oacc[h][n][2], oacc[h][n][3]);
        }
    }
}

// ---------------------------------------------------------------------------
// Combine: out = (sum_z O_z) / (sum_z l_z)   (partials are L2-resident)
// ---------------------------------------------------------------------------
__global__ __launch_bounds__(256) void combine_kernel(float* __restrict__ out)
{
    const int idx = blockIdx.x * blockDim.x + threadIdx.x;  // 262144 float4
    const int row = idx >> 4;
    const int c4  = idx & 15;
    const size_t stride = (size_t)BATCH * SEQ;

    float l = 0.0f;
    float4 o = make_float4(0.f, 0.f, 0.f, 0.f);
    #pragma unroll
    for (int zz = 0; zz < NSPLIT; zz++) {
        l += g_lsum[zz * stride + row];
        float4 p = *reinterpret_cast<const float4*>(
            &g_part[(zz * stride + row) * HD + c4 * 4]);
        o.x += p.x; o.y += p.y; o.z += p.z; o.w += p.w;
    }
    float inv = 1.0f / l;
    o.x *= inv; o.y *= inv; o.z *= inv; o.w *= inv;
    *reinterpret_cast<float4*>(&out[(size_t)row * HD + c4 * 4]) = o;
}

// ---------------------------------------------------------------------------
extern "C" void kernel_launch(void* const* d_in, const int* in_sizes, int n_in,
                              void* d_out, int out_size)
{
    const float* x  = (const float*)d_in[0];
    const float* WQ = (const float*)d_in[1];
    const float* WK = (const float*)d_in[2];
    const float* WV = (const float*)d_in[3];
    float* out = (float*)d_out;

    cudaFuncSetAttribute(proj_mma_kernel,
                         cudaFuncAttributeMaxDynamicSharedMemorySize,
                         PROJ_SMEM_BYTES);
    cudaFuncSetAttribute(attn_mma_kernel,
                         cudaFuncAttributeMaxDynamicSharedMemorySize,
                         ATTN_SMEM_BYTES);

    wcvt_kernel<<<96, 256>>>(WQ, WK, WV);
    proj_mma_kernel<<<dim3(SEQ * BATCH / 64, 3), 64, PROJ_SMEM_BYTES>>>(x);
    attn_mma_kernel<<<dim3(SEQ / 128, BATCH, NSPLIT), 128, ATTN_SMEM_BYTES>>>();
    combine_kernel<<<(BATCH * SEQ * HD / 4) / 256, 256>>>(out);
}

// round 9
// speedup vs baseline: 1.1496x; 1.1496x over previous
#include <cuda_runtime.h>
#include <math.h>

#define BATCH 4
#define SEQ   4096
#define EMB   512
#define HD    64
#define NSPLIT 7

__device__ float g_q[BATCH * SEQ * HD];
__device__ float g_k[BATCH * SEQ * HD];
__device__ float g_v[BATCH * SEQ * HD];
__device__ float g_part[NSPLIT * BATCH * SEQ * HD];   // unnormalized O partials
__device__ float g_lsum[NSPLIT * BATCH * SEQ];        // exp-sum partials

// ---------------------------------------------------------------------------
__device__ __forceinline__ unsigned f2tf(float x) {
    unsigned r;
    asm("cvt.rna.tf32.f32 %0, %1;" : "=r"(r) : "f"(x));
    return r;
}
__device__ __forceinline__ float ex2(float x) {
    float r;
    asm("ex2.approx.ftz.f32 %0, %1;" : "=f"(r) : "f"(x));
    return r;
}

__device__ __forceinline__ void mma_tf32(float c[4],
                                         unsigned a0, unsigned a1,
                                         unsigned a2, unsigned a3,
                                         unsigned b0, unsigned b1) {
    asm volatile(
        "mma.sync.aligned.m16n8k8.row.col.f32.tf32.tf32.f32 "
        "{%0,%1,%2,%3}, {%4,%5,%6,%7}, {%8,%9}, {%0,%1,%2,%3};"
        : "+f"(c[0]), "+f"(c[1]), "+f"(c[2]), "+f"(c[3])
        : "r"(a0), "r"(a1), "r"(a2), "r"(a3), "r"(b0), "r"(b1));
}

#define CP_COMMIT() asm volatile("cp.async.commit_group;" ::: "memory")
#define CP_WAIT1()  asm volatile("cp.async.wait_group 1;" ::: "memory")

// ---------------------------------------------------------------------------
// tf32 projection: C[16384,64] = X[16384,512] * W[64,512]^T.
// CTA = 128 threads / 4 warps, m32 warp tiles over a 128-row X tile, so the
// W B-fragments amortize over both m16 halves (1.5 LDS/mma). Single-buffered
// smem, one full wave at 3 CTAs/SM; convert-at-STS; kc-outer register economy.
// ---------------------------------------------------------------------------
#define PPX 68
#define PROJ_SMEM_FLOATS (128 * PPX + 64 * PPX)
#define PROJ_SMEM_BYTES  (PROJ_SMEM_FLOATS * 4)
#define PNCHUNK (EMB / 64)   // 8

__global__ __launch_bounds__(128, 3) void proj_mma_kernel(
    const float* __restrict__ x,
    const float* __restrict__ WQ,
    const float* __restrict__ WK,
    const float* __restrict__ WV)
{
    extern __shared__ float psm[];
    float* Xs = psm;                // 128 x PPX (tf32 bits)
    float* Ws = psm + 128 * PPX;    // 64 x PPX (tf32 bits)

    const float* W;
    float* out;
    if (blockIdx.y == 0)      { W = WQ; out = g_q; }
    else if (blockIdx.y == 1) { W = WK; out = g_k; }
    else                      { W = WV; out = g_v; }

    const int tid  = threadIdx.x;
    const int lane = tid & 31;
    const int warp = tid >> 5;
    const int g    = lane >> 2;
    const int tq   = lane & 3;
    const int bm   = blockIdx.x * 128;
    const int rw   = 32 * warp;

    const unsigned* Xu = reinterpret_cast<const unsigned*>(Xs);
    const unsigned* Wu = reinterpret_cast<const unsigned*>(Ws);

    float acc[2][8][4];
    #pragma unroll
    for (int h = 0; h < 2; h++)
        #pragma unroll
        for (int n = 0; n < 8; n++)
            #pragma unroll
            for (int j = 0; j < 4; j++) acc[h][n][j] = 0.0f;

    for (int c = 0; c < PNCHUNK; c++) {
        const int k0 = c * 64;
        __syncthreads();   // previous chunk's fragment reads done
        // X tile: 128 rows x 16 float4
        #pragma unroll
        for (int i = 0; i < 16; i++) {
            int f = tid + 128 * i;
            int row = f >> 4, c4 = f & 15;
            float4 v = *reinterpret_cast<const float4*>(
                &x[(size_t)(bm + row) * EMB + k0 + c4 * 4]);
            uint4 t = { f2tf(v.x), f2tf(v.y), f2tf(v.z), f2tf(v.w) };
            *reinterpret_cast<uint4*>(&Xs[row * PPX + c4 * 4]) = t;
        }
        // W tile: 64 rows x 16 float4
        #pragma unroll
        for (int i = 0; i < 8; i++) {
            int f = tid + 128 * i;
            int row = f >> 4, c4 = f & 15;
            float4 v = *reinterpret_cast<const float4*>(
                &W[(size_t)row * EMB + k0 + c4 * 4]);
            uint4 t = { f2tf(v.x), f2tf(v.y), f2tf(v.z), f2tf(v.w) };
            *reinterpret_cast<uint4*>(&Ws[row * PPX + c4 * 4]) = t;
        }
        __syncthreads();

        #pragma unroll
        for (int kc = 0; kc < 8; kc++) {
            unsigned xa[2][4];
            #pragma unroll
            for (int h = 0; h < 2; h++) {
                int ra = rw + 16 * h + g;
                xa[h][0] = Xu[(ra)     * PPX + 8 * kc + tq];
                xa[h][1] = Xu[(ra + 8) * PPX + 8 * kc + tq];
                xa[h][2] = Xu[(ra)     * PPX + 8 * kc + tq + 4];
                xa[h][3] = Xu[(ra + 8) * PPX + 8 * kc + tq + 4];
            }
            #pragma unroll
            for (int n = 0; n < 8; n++) {
                unsigned b0 = Wu[(8 * n + g) * PPX + 8 * kc + tq];
                unsigned b1 = Wu[(8 * n + g) * PPX + 8 * kc + tq + 4];
                mma_tf32(acc[0][n], xa[0][0], xa[0][1], xa[0][2], xa[0][3], b0, b1);
                mma_tf32(acc[1][n], xa[1][0], xa[1][1], xa[1][2], xa[1][3], b0, b1);
            }
        }
    }

    // store PRE-ROUNDED tf32 (attention consumes without cvt)
    #pragma unroll
    for (int h = 0; h < 2; h++) {
        int ra = rw + 16 * h + g;
        float* o0 = out + (size_t)(bm + ra)     * HD;
        float* o1 = out + (size_t)(bm + ra + 8) * HD;
        #pragma unroll
        for (int n = 0; n < 8; n++) {
            int cc = 8 * n + 2 * tq;
            float2 w0 = { __uint_as_float(f2tf(acc[h][n][0])),
                          __uint_as_float(f2tf(acc[h][n][1])) };
            float2 w1 = { __uint_as_float(f2tf(acc[h][n][2])),
                          __uint_as_float(f2tf(acc[h][n][3])) };
            *reinterpret_cast<float2*>(&o0[cc]) = w0;
            *reinterpret_cast<float2*>(&o1[cc]) = w1;
        }
    }
}

// ---------------------------------------------------------------------------
// Attention (R7 config): tf32 mma, m32 warp tile, CTA = 128 Q rows / 4 warps,
// split-KV NSPLIT=7, cp.async double-buffered K/V, shuffle S->P conversion,
// P fed as raw fp32 bits (HW tf32 truncation), no-max softmax.
// ---------------------------------------------------------------------------
#define PK   68
#define PV   72
#define KBUF (64 * PK)
#define VBUF (64 * PV)
#define ATTN_SMEM_BYTES ((2 * KBUF + 2 * VBUF) * 4)

__device__ __forceinline__ void attn_load_async(float* Kd, float* Vd,
                                                const float* kg, const float* vg,
                                                int tid) {
    unsigned ka = (unsigned)__cvta_generic_to_shared(Kd);
    unsigned va = (unsigned)__cvta_generic_to_shared(Vd);
    #pragma unroll
    for (int i = 0; i < 8; i++) {
        int f = tid + 128 * i;           // 1024 float4 = 64 rows x 16
        int row = f >> 4, c4 = f & 15;
        asm volatile("cp.async.cg.shared.global [%0], [%1], 16;" ::
            "r"(ka + (unsigned)((row * PK + c4 * 4) * 4)),
            "l"(kg + row * HD + c4 * 4) : "memory");
        asm volatile("cp.async.cg.shared.global [%0], [%1], 16;" ::
            "r"(va + (unsigned)((row * PV + c4 * 4) * 4)),
            "l"(vg + row * HD + c4 * 4) : "memory");
    }
}

__global__ __launch_bounds__(128) void attn_mma_kernel()
{
    extern __shared__ float sm[];
    float* Kb[2] = { sm, sm + KBUF };
    float* Vb[2] = { sm + 2 * KBUF, sm + 2 * KBUF + VBUF };

    const int tid  = threadIdx.x;
    const int lane = tid & 31;
    const int warp = tid >> 5;
    const int g    = lane >> 2;
    const int tq   = lane & 3;
    const int b    = blockIdx.y;
    const int q0   = blockIdx.x * 128;
    const int z    = blockIdx.z;
    const int t_begin = (64 * z) / NSPLIT;
    const int t_end   = (64 * (z + 1)) / NSPLIT;
    const int nt      = t_end - t_begin;

    const float* qg  = g_q + ((size_t)b * SEQ + q0) * HD;
    const float* kgb = g_k + ((size_t)b * SEQ + (size_t)t_begin * 64) * HD;
    const float* vgb = g_v + ((size_t)b * SEQ + (size_t)t_begin * 64) * HD;

    const int rw = 32 * warp;
    unsigned qa[2][8][4];
    #pragma unroll
    for (int h = 0; h < 2; h++) {
        int ra = rw + 16 * h + g;
        #pragma unroll
        for (int ks = 0; ks < 8; ks++) {
            qa[h][ks][0] = __float_as_uint(qg[(ra)     * HD + 8 * ks + tq]);
            qa[h][ks][1] = __float_as_uint(qg[(ra + 8) * HD + 8 * ks + tq]);
            qa[h][ks][2] = __float_as_uint(qg[(ra)     * HD + 8 * ks + tq + 4]);
            qa[h][ks][3] = __float_as_uint(qg[(ra + 8) * HD + 8 * ks + tq + 4]);
        }
    }

    float oacc[2][8][4];
    #pragma unroll
    for (int h = 0; h < 2; h++)
        #pragma unroll
        for (int n = 0; n < 8; n++)
            #pragma unroll
            for (int j = 0; j < 4; j++) oacc[h][n][j] = 0.0f;
    float ls[2][2] = {{0.f, 0.f}, {0.f, 0.f}};

    attn_load_async(Kb[0], Vb[0], kgb, vgb, tid);
    CP_COMMIT();

    const float C = 0.18033688f;   // 0.125 * log2(e)

    for (int tt = 0; tt < nt; tt++) {
        __syncthreads();
        if (tt + 1 < nt)
            attn_load_async(Kb[(tt + 1) & 1], Vb[(tt + 1) & 1],
                            kgb + (size_t)(tt + 1) * 64 * HD,
                            vgb + (size_t)(tt + 1) * 64 * HD, tid);
        CP_COMMIT();
        CP_WAIT1();
        __syncthreads();

        const unsigned* Ku = reinterpret_cast<const unsigned*>(Kb[tt & 1]);
        const unsigned* Vu = reinterpret_cast<const unsigned*>(Vb[tt & 1]);

        #pragma unroll
        for (int nb = 0; nb < 8; nb++) {
            // ---- S block: both halves share the K B-fragments ----
            float cf[2][4] = {{0.f,0.f,0.f,0.f},{0.f,0.f,0.f,0.f}};
            #pragma unroll
            for (int kc = 0; kc < 8; kc++) {
                unsigned b0 = Ku[(8 * nb + g) * PK + 8 * kc + tq];
                unsigned b1 = Ku[(8 * nb + g) * PK + 8 * kc + tq + 4];
                mma_tf32(cf[0], qa[0][kc][0], qa[0][kc][1], qa[0][kc][2], qa[0][kc][3], b0, b1);
                mma_tf32(cf[1], qa[1][kc][0], qa[1][kc][1], qa[1][kc][2], qa[1][kc][3], b0, b1);
            }

            // ---- exp + C-frag -> A-frag conversion; P passed as raw bits ----
            unsigned pa[2][4];
            #pragma unroll
            for (int h = 0; h < 2; h++) {
                float e0 = ex2(cf[h][0] * C);
                float e1 = ex2(cf[h][1] * C);
                float e2 = ex2(cf[h][2] * C);
                float e3 = ex2(cf[h][3] * C);
                ls[h][0] += e0 + e1;
                ls[h][1] += e2 + e3;
                int hh = tq >> 1;
                float a0  = __shfl_sync(0xffffffffu, e0, hh, 4);
                float a1  = __shfl_sync(0xffffffffu, e1, hh, 4);
                float b0f = __shfl_sync(0xffffffffu, e0, hh + 2, 4);
                float b1f = __shfl_sync(0xffffffffu, e1, hh + 2, 4);
                float c0f = __shfl_sync(0xffffffffu, e2, hh, 4);
                float c1f = __shfl_sync(0xffffffffu, e3, hh, 4);
                float d0f = __shfl_sync(0xffffffffu, e2, hh + 2, 4);
                float d1f = __shfl_sync(0xffffffffu, e3, hh + 2, 4);
                bool odd = (tq & 1);
                pa[h][0] = __float_as_uint(odd ? a1  : a0);    // P[rA][8nb+tq]
                pa[h][1] = __float_as_uint(odd ? c1f : c0f);   // P[rB][8nb+tq]
                pa[h][2] = __float_as_uint(odd ? b1f : b0f);   // P[rA][8nb+tq+4]
                pa[h][3] = __float_as_uint(odd ? d1f : d0f);   // P[rB][8nb+tq+4]
            }

            // ---- O += P(:,nb) * V(nb,:) ; both halves share V B-frags ----
            #pragma unroll
            for (int nd = 0; nd < 8; nd++) {
                unsigned vb0 = Vu[(8 * nb + tq)     * PV + 8 * nd + g];
                unsigned vb1 = Vu[(8 * nb + tq + 4) * PV + 8 * nd + g];
                mma_tf32(oacc[0][nd], pa[0][0], pa[0][1], pa[0][2], pa[0][3], vb0, vb1);
                mma_tf32(oacc[1][nd], pa[1][0], pa[1][1], pa[1][2], pa[1][3], vb0, vb1);
            }
        }
    }

    // ---- epilogue: quad-reduce sums, write unnormalized partials ----
    const size_t rowbase = (size_t)z * BATCH * SEQ + (size_t)b * SEQ + q0;
    #pragma unroll
    for (int h = 0; h < 2; h++) {
        float l0 = ls[h][0], l1 = ls[h][1];
        l0 += __shfl_xor_sync(0xffffffffu, l0, 1);
        l0 += __shfl_xor_sync(0xffffffffu, l0, 2);
        l1 += __shfl_xor_sync(0xffffffffu, l1, 1);
        l1 += __shfl_xor_sync(0xffffffffu, l1, 2);
        int ra = rw + 16 * h + g;
        if (tq == 0) {
            g_lsum[rowbase + ra]     = l0;
            g_lsum[rowbase + ra + 8] = l1;
        }
        float* o0 = g_part + (rowbase + ra)     * HD;
        float* o1 = g_part + (rowbase + ra + 8) * HD;
        #pragma unroll
        for (int n = 0; n < 8; n++) {
            int cc = 8 * n + 2 * tq;
            *reinterpret_cast<float2*>(&o0[cc]) = make_float2(oacc[h][n][0], oacc[h][n][1]);
            *reinterpret_cast<float2*>(&o1[cc]) = make_float2(oacc[h][n][2], oacc[h][n][3]);
        }
    }
}

// ---------------------------------------------------------------------------
// Combine: out = (sum_z O_z) / (sum_z l_z)
// ---------------------------------------------------------------------------
__global__ __launch_bounds__(256) void combine_kernel(float* __restrict__ out)
{
    const int idx = blockIdx.x * blockDim.x + threadIdx.x;  // 262144 float4
    const int row = idx >> 4;
    const int c4  = idx & 15;
    const size_t stride = (size_t)BATCH * SEQ;

    float l = 0.0f;
    float4 o = make_float4(0.f, 0.f, 0.f, 0.f);
    #pragma unroll
    for (int zz = 0; zz < NSPLIT; zz++) {
        l += g_lsum[zz * stride + row];
        float4 p = *reinterpret_cast<const float4*>(
            &g_part[(zz * stride + row) * HD + c4 * 4]);
        o.x += p.x; o.y += p.y; o.z += p.z; o.w += p.w;
    }
    float inv = 1.0f / l;
    o.x *= inv; o.y *= inv; o.z *= inv; o.w *= inv;
    *reinterpret_cast<float4*>(&out[(size_t)row * HD + c4 * 4]) = o;
}

// ---------------------------------------------------------------------------
extern "C" void kernel_launch(void* const* d_in, const int* in_sizes, int n_in,
                              void* d_out, int out_size)
{
    const float* x  = (const float*)d_in[0];
    const float* WQ = (const float*)d_in[1];
    const float* WK = (const float*)d_in[2];
    const float* WV = (const float*)d_in[3];
    float* out = (float*)d_out;

    cudaFuncSetAttribute(proj_mma_kernel,
                         cudaFuncAttributeMaxDynamicSharedMemorySize,
                         PROJ_SMEM_BYTES);
    cudaFuncSetAttribute(attn_mma_kernel,
                         cudaFuncAttributeMaxDynamicSharedMemorySize,
                         ATTN_SMEM_BYTES);

    proj_mma_kernel<<<dim3(SEQ * BATCH / 128, 3), 128, PROJ_SMEM_BYTES>>>(x, WQ, WK, WV);
    attn_mma_kernel<<<dim3(SEQ / 128, BATCH, NSPLIT), 128, ATTN_SMEM_BYTES>>>();
    combine_kernel<<<(BATCH * SEQ * HD / 4) / 256, 256>>>(out);
}

// round 10
// speedup vs baseline: 1.3410x; 1.1665x over previous
#include <cuda_runtime.h>
#include <math.h>

#define BATCH 4
#define SEQ   4096
#define EMB   512
#define HD    64
#define NSPLIT 7

__device__ float g_q[BATCH * SEQ * HD];
__device__ float g_k[BATCH * SEQ * HD];
__device__ float g_v[BATCH * SEQ * HD];
__device__ float g_part[NSPLIT * BATCH * SEQ * HD];   // unnormalized O partials
__device__ float g_lsum[NSPLIT * BATCH * SEQ];        // exp-sum partials

// ---------------------------------------------------------------------------
__device__ __forceinline__ unsigned f2tf(float x) {
    unsigned r;
    asm("cvt.rna.tf32.f32 %0, %1;" : "=r"(r) : "f"(x));
    return r;
}
__device__ __forceinline__ float ex2(float x) {
    float r;
    asm("ex2.approx.ftz.f32 %0, %1;" : "=f"(r) : "f"(x));
    return r;
}

__device__ __forceinline__ void mma_tf32(float c[4],
                                         unsigned a0, unsigned a1,
                                         unsigned a2, unsigned a3,
                                         unsigned b0, unsigned b1) {
    asm volatile(
        "mma.sync.aligned.m16n8k8.row.col.f32.tf32.tf32.f32 "
        "{%0,%1,%2,%3}, {%4,%5,%6,%7}, {%8,%9}, {%0,%1,%2,%3};"
        : "+f"(c[0]), "+f"(c[1]), "+f"(c[2]), "+f"(c[3])
        : "r"(a0), "r"(a1), "r"(a2), "r"(a3), "r"(b0), "r"(b1));
}

#define CP_COMMIT() asm volatile("cp.async.commit_group;" ::: "memory")
#define CP_WAIT1()  asm volatile("cp.async.wait_group 1;" ::: "memory")

// ---------------------------------------------------------------------------
// tf32 projection (unchanged from R9): CTA = 128 thr / 4 warps, m32 warp
// tiles over a 128-row X tile, single-buffered, convert-at-STS.
// ---------------------------------------------------------------------------
#define PPX 68
#define PROJ_SMEM_FLOATS (128 * PPX + 64 * PPX)
#define PROJ_SMEM_BYTES  (PROJ_SMEM_FLOATS * 4)
#define PNCHUNK (EMB / 64)   // 8

__global__ __launch_bounds__(128, 3) void proj_mma_kernel(
    const float* __restrict__ x,
    const float* __restrict__ WQ,
    const float* __restrict__ WK,
    const float* __restrict__ WV)
{
    extern __shared__ float psm[];
    float* Xs = psm;                // 128 x PPX (tf32 bits)
    float* Ws = psm + 128 * PPX;    // 64 x PPX (tf32 bits)

    const float* W;
    float* out;
    if (blockIdx.y == 0)      { W = WQ; out = g_q; }
    else if (blockIdx.y == 1) { W = WK; out = g_k; }
    else                      { W = WV; out = g_v; }

    const int tid  = threadIdx.x;
    const int lane = tid & 31;
    const int warp = tid >> 5;
    const int g    = lane >> 2;
    const int tq   = lane & 3;
    const int bm   = blockIdx.x * 128;
    const int rw   = 32 * warp;

    const unsigned* Xu = reinterpret_cast<const unsigned*>(Xs);
    const unsigned* Wu = reinterpret_cast<const unsigned*>(Ws);

    float acc[2][8][4];
    #pragma unroll
    for (int h = 0; h < 2; h++)
        #pragma unroll
        for (int n = 0; n < 8; n++)
            #pragma unroll
            for (int j = 0; j < 4; j++) acc[h][n][j] = 0.0f;

    for (int c = 0; c < PNCHUNK; c++) {
        const int k0 = c * 64;
        __syncthreads();
        #pragma unroll
        for (int i = 0; i < 16; i++) {
            int f = tid + 128 * i;
            int row = f >> 4, c4 = f & 15;
            float4 v = *reinterpret_cast<const float4*>(
                &x[(size_t)(bm + row) * EMB + k0 + c4 * 4]);
            uint4 t = { f2tf(v.x), f2tf(v.y), f2tf(v.z), f2tf(v.w) };
            *reinterpret_cast<uint4*>(&Xs[row * PPX + c4 * 4]) = t;
        }
        #pragma unroll
        for (int i = 0; i < 8; i++) {
            int f = tid + 128 * i;
            int row = f >> 4, c4 = f & 15;
            float4 v = *reinterpret_cast<const float4*>(
                &W[(size_t)row * EMB + k0 + c4 * 4]);
            uint4 t = { f2tf(v.x), f2tf(v.y), f2tf(v.z), f2tf(v.w) };
            *reinterpret_cast<uint4*>(&Ws[row * PPX + c4 * 4]) = t;
        }
        __syncthreads();

        #pragma unroll
        for (int kc = 0; kc < 8; kc++) {
            unsigned xa[2][4];
            #pragma unroll
            for (int h = 0; h < 2; h++) {
                int ra = rw + 16 * h + g;
                xa[h][0] = Xu[(ra)     * PPX + 8 * kc + tq];
                xa[h][1] = Xu[(ra + 8) * PPX + 8 * kc + tq];
                xa[h][2] = Xu[(ra)     * PPX + 8 * kc + tq + 4];
                xa[h][3] = Xu[(ra + 8) * PPX + 8 * kc + tq + 4];
            }
            #pragma unroll
            for (int n = 0; n < 8; n++) {
                unsigned b0 = Wu[(8 * n + g) * PPX + 8 * kc + tq];
                unsigned b1 = Wu[(8 * n + g) * PPX + 8 * kc + tq + 4];
                mma_tf32(acc[0][n], xa[0][0], xa[0][1], xa[0][2], xa[0][3], b0, b1);
                mma_tf32(acc[1][n], xa[1][0], xa[1][1], xa[1][2], xa[1][3], b0, b1);
            }
        }
    }

    #pragma unroll
    for (int h = 0; h < 2; h++) {
        int ra = rw + 16 * h + g;
        float* o0 = out + (size_t)(bm + ra)     * HD;
        float* o1 = out + (size_t)(bm + ra + 8) * HD;
        #pragma unroll
        for (int n = 0; n < 8; n++) {
            int cc = 8 * n + 2 * tq;
            float2 w0 = { __uint_as_float(f2tf(acc[h][n][0])),
                          __uint_as_float(f2tf(acc[h][n][1])) };
            float2 w1 = { __uint_as_float(f2tf(acc[h][n][2])),
                          __uint_as_float(f2tf(acc[h][n][3])) };
            *reinterpret_cast<float2*>(&o0[cc]) = w0;
            *reinterpret_cast<float2*>(&o1[cc]) = w1;
        }
    }
}

// ---------------------------------------------------------------------------
// Attention: tf32 mma, m32 warp tile, split-KV NSPLIT=7, cp.async
// double-buffered K/V. SHUFFLE-FREE S->P: the S C-fragment is fed directly
// as the PV A-fragment (pa = {e0,e2,e1,e3}); the implied column permutation
// sigma(p) = (p>>1)+4*(p&1) is absorbed into the V smem row index
// (rows 8nb+2tq / 8nb+2tq+1). PV pitch 68 keeps those reads conflict-free.
// ---------------------------------------------------------------------------
#define PK   68
#define PV   68
#define KBUF (64 * PK)
#define VBUF (64 * PV)
#define ATTN_SMEM_BYTES ((2 * KBUF + 2 * VBUF) * 4)

__device__ __forceinline__ void attn_load_async(float* Kd, float* Vd,
                                                const float* kg, const float* vg,
                                                int tid) {
    unsigned ka = (unsigned)__cvta_generic_to_shared(Kd);
    unsigned va = (unsigned)__cvta_generic_to_shared(Vd);
    #pragma unroll
    for (int i = 0; i < 8; i++) {
        int f = tid + 128 * i;           // 1024 float4 = 64 rows x 16
        int row = f >> 4, c4 = f & 15;
        asm volatile("cp.async.cg.shared.global [%0], [%1], 16;" ::
            "r"(ka + (unsigned)((row * PK + c4 * 4) * 4)),
            "l"(kg + row * HD + c4 * 4) : "memory");
        asm volatile("cp.async.cg.shared.global [%0], [%1], 16;" ::
            "r"(va + (unsigned)((row * PV + c4 * 4) * 4)),
            "l"(vg + row * HD + c4 * 4) : "memory");
    }
}

__global__ __launch_bounds__(128) void attn_mma_kernel()
{
    extern __shared__ float sm[];
    float* Kb[2] = { sm, sm + KBUF };
    float* Vb[2] = { sm + 2 * KBUF, sm + 2 * KBUF + VBUF };

    const int tid  = threadIdx.x;
    const int lane = tid & 31;
    const int warp = tid >> 5;
    const int g    = lane >> 2;
    const int tq   = lane & 3;
    const int b    = blockIdx.y;
    const int q0   = blockIdx.x * 128;
    const int z    = blockIdx.z;
    const int t_begin = (64 * z) / NSPLIT;
    const int t_end   = (64 * (z + 1)) / NSPLIT;
    const int nt      = t_end - t_begin;

    const float* qg  = g_q + ((size_t)b * SEQ + q0) * HD;
    const float* kgb = g_k + ((size_t)b * SEQ + (size_t)t_begin * 64) * HD;
    const float* vgb = g_v + ((size_t)b * SEQ + (size_t)t_begin * 64) * HD;

    const int rw = 32 * warp;
    unsigned qa[2][8][4];
    #pragma unroll
    for (int h = 0; h < 2; h++) {
        int ra = rw + 16 * h + g;
        #pragma unroll
        for (int ks = 0; ks < 8; ks++) {
            qa[h][ks][0] = __float_as_uint(qg[(ra)     * HD + 8 * ks + tq]);
            qa[h][ks][1] = __float_as_uint(qg[(ra + 8) * HD + 8 * ks + tq]);
            qa[h][ks][2] = __float_as_uint(qg[(ra)     * HD + 8 * ks + tq + 4]);
            qa[h][ks][3] = __float_as_uint(qg[(ra + 8) * HD + 8 * ks + tq + 4]);
        }
    }

    float oacc[2][8][4];
    #pragma unroll
    for (int h = 0; h < 2; h++)
        #pragma unroll
        for (int n = 0; n < 8; n++)
            #pragma unroll
            for (int j = 0; j < 4; j++) oacc[h][n][j] = 0.0f;
    float ls[2][2] = {{0.f, 0.f}, {0.f, 0.f}};

    attn_load_async(Kb[0], Vb[0], kgb, vgb, tid);
    CP_COMMIT();

    const float C = 0.18033688f;   // 0.125 * log2(e)

    for (int tt = 0; tt < nt; tt++) {
        __syncthreads();
        if (tt + 1 < nt)
            attn_load_async(Kb[(tt + 1) & 1], Vb[(tt + 1) & 1],
                            kgb + (size_t)(tt + 1) * 64 * HD,
                            vgb + (size_t)(tt + 1) * 64 * HD, tid);
        CP_COMMIT();
        CP_WAIT1();
        __syncthreads();

        const unsigned* Ku = reinterpret_cast<const unsigned*>(Kb[tt & 1]);
        const unsigned* Vu = reinterpret_cast<const unsigned*>(Vb[tt & 1]);

        #pragma unroll
        for (int nb = 0; nb < 8; nb++) {
            // ---- S block: both halves share the K B-fragments ----
            float cf[2][4] = {{0.f,0.f,0.f,0.f},{0.f,0.f,0.f,0.f}};
            #pragma unroll
            for (int kc = 0; kc < 8; kc++) {
                unsigned b0 = Ku[(8 * nb + g) * PK + 8 * kc + tq];
                unsigned b1 = Ku[(8 * nb + g) * PK + 8 * kc + tq + 4];
                mma_tf32(cf[0], qa[0][kc][0], qa[0][kc][1], qa[0][kc][2], qa[0][kc][3], b0, b1);
                mma_tf32(cf[1], qa[1][kc][0], qa[1][kc][1], qa[1][kc][2], qa[1][kc][3], b0, b1);
            }

            // ---- exp; C-fragment IS the PV A-fragment (no shuffles) ----
            unsigned pa[2][4];
            #pragma unroll
            for (int h = 0; h < 2; h++) {
                float e0 = ex2(cf[h][0] * C);   // P[rA][phys 2tq]
                float e1 = ex2(cf[h][1] * C);   // P[rA][phys 2tq+1]
                float e2 = ex2(cf[h][2] * C);   // P[rB][phys 2tq]
                float e3 = ex2(cf[h][3] * C);   // P[rB][phys 2tq+1]
                ls[h][0] += e0 + e1;
                ls[h][1] += e2 + e3;
                pa[h][0] = __float_as_uint(e0); // A[rA][log tq]
                pa[h][1] = __float_as_uint(e2); // A[rB][log tq]
                pa[h][2] = __float_as_uint(e1); // A[rA][log tq+4]
                pa[h][3] = __float_as_uint(e3); // A[rB][log tq+4]
            }

            // ---- O += P(:,nb) * V(nb,:) with sigma-permuted V rows ----
            const unsigned* vr0 = Vu + (8 * nb + 2 * tq)     * PV;  // log tq
            const unsigned* vr1 = Vu + (8 * nb + 2 * tq + 1) * PV;  // log tq+4
            #pragma unroll
            for (int nd = 0; nd < 8; nd++) {
                unsigned vb0 = vr0[8 * nd + g];
                unsigned vb1 = vr1[8 * nd + g];
                mma_tf32(oacc[0][nd], pa[0][0], pa[0][1], pa[0][2], pa[0][3], vb0, vb1);
                mma_tf32(oacc[1][nd], pa[1][0], pa[1][1], pa[1][2], pa[1][3], vb0, vb1);
            }
        }
    }

    // ---- epilogue: quad-reduce sums, write unnormalized partials ----
    const size_t rowbase = (size_t)z * BATCH * SEQ + (size_t)b * SEQ + q0;
    #pragma unroll
    for (int h = 0; h < 2; h++) {
        float l0 = ls[h][0], l1 = ls[h][1];
        l0 += __shfl_xor_sync(0xffffffffu, l0, 1);
        l0 += __shfl_xor_sync(0xffffffffu, l0, 2);
        l1 += __shfl_xor_sync(0xffffffffu, l1, 1);
        l1 += __shfl_xor_sync(0xffffffffu, l1, 2);
        int ra = rw + 16 * h + g;
        if (tq == 0) {
            g_lsum[rowbase + ra]     = l0;
            g_lsum[rowbase + ra + 8] = l1;
        }
        float* o0 = g_part + (rowbase + ra)     * HD;
        float* o1 = g_part + (rowbase + ra + 8) * HD;
        #pragma unroll
        for (int n = 0; n < 8; n++) {
            int cc = 8 * n + 2 * tq;
            *reinterpret_cast<float2*>(&o0[cc]) = make_float2(oacc[h][n][0], oacc[h][n][1]);
            *reinterpret_cast<float2*>(&o1[cc]) = make_float2(oacc[h][n][2], oacc[h][n][3]);
        }
    }
}

// ---------------------------------------------------------------------------
// Combine: out = (sum_z O_z) / (sum_z l_z)
// ---------------------------------------------------------------------------
__global__ __launch_bounds__(256) void combine_kernel(float* __restrict__ out)
{
    const int idx = blockIdx.x * blockDim.x + threadIdx.x;  // 262144 float4
    const int row = idx >> 4;
    const int c4  = idx & 15;
    const size_t stride = (size_t)BATCH * SEQ;

    float l = 0.0f;
    float4 o = make_float4(0.f, 0.f, 0.f, 0.f);
    #pragma unroll
    for (int zz = 0; zz < NSPLIT; zz++) {
        l += g_lsum[zz * stride + row];
        float4 p = *reinterpret_cast<const float4*>(
            &g_part[(zz * stride + row) * HD + c4 * 4]);
        o.x += p.x; o.y += p.y; o.z += p.z; o.w += p.w;
    }
    float inv = 1.0f / l;
    o.x *= inv; o.y *= inv; o.z *= inv; o.w *= inv;
    *reinterpret_cast<float4*>(&out[(size_t)row * HD + c4 * 4]) = o;
}

// ---------------------------------------------------------------------------
extern "C" void kernel_launch(void* const* d_in, const int* in_sizes, int n_in,
                              void* d_out, int out_size)
{
    const float* x  = (const float*)d_in[0];
    const float* WQ = (const float*)d_in[1];
    const float* WK = (const float*)d_in[2];
    const float* WV = (const float*)d_in[3];
    float* out = (float*)d_out;

    cudaFuncSetAttribute(proj_mma_kernel,
                         cudaFuncAttributeMaxDynamicSharedMemorySize,
                         PROJ_SMEM_BYTES);
    cudaFuncSetAttribute(attn_mma_kernel,
                         cudaFuncAttributeMaxDynamicSharedMemorySize,
                         ATTN_SMEM_BYTES);

    proj_mma_kernel<<<dim3(SEQ * BATCH / 128, 3), 128, PROJ_SMEM_BYTES>>>(x, WQ, WK, WV);
    attn_mma_kernel<<<dim3(SEQ / 128, BATCH, NSPLIT), 128, ATTN_SMEM_BYTES>>>();
    combine_kernel<<<(BATCH * SEQ * HD / 4) / 256, 256>>>(out);
}